// round 11
// baseline (speedup 1.0000x reference)
#include <cuda_runtime.h>
#include <cuda_bf16.h>
#include <cuda_fp16.h>
#include <cstdint>

#define D   512
#define F   2000
#define NF  16
#define KNN 8
#define SL  16
#define FP  2048

// ---- scratch ----
__device__ float         g_T [(size_t)NF * F * D];
__device__ __nv_bfloat16 g_Tb[(size_t)NF * F * D];
__device__ float         g_sq[NF * F];
__device__ __half        g_scoresh[(size_t)NF * FP * FP];  // raw dots, fp16
__device__ int           g_cand[NF * F * SL];
__device__ int           g_idx [F * KNN * NF];
__device__ float         g_dummy_sink;

#define SENT 0xFF800000FFFFFFFFull
#define FULLM 0xFFFFFFFFu

// ---- smem for k_gemm: 3-stage rings, A(64x80B) + B(128x80B) ----
#define SM_A    0         // 3 x 5120  = 15360
#define SM_B    15360     // 3 x 10240 = 30720
#define SM_TOTAL 46080
#define BUFA    5120u
#define BUFB    10240u

__device__ __forceinline__ uint32_t smem_u32(const void* p) {
    uint32_t a;
    asm("{ .reg .u64 t; cvta.to.shared.u64 t, %1; cvt.u32.u64 %0, t; }"
        : "=r"(a) : "l"(p));
    return a;
}
#define CP16(dst, src) \
    asm volatile("cp.async.cg.shared.global [%0], [%1], 16;" :: "r"(dst), "l"(src))
#define CP_COMMIT() asm volatile("cp.async.commit_group;" ::: "memory")
#define CP_WAIT0()  asm volatile("cp.async.wait_group 0;" ::: "memory")
#define CP_WAIT1()  asm volatile("cp.async.wait_group 1;" ::: "memory")
#define LDSM4(r0, r1, r2, r3, a) \
    asm volatile("ldmatrix.sync.aligned.m8n8.x4.shared.b16 {%0,%1,%2,%3}, [%4];" \
        : "=r"(r0), "=r"(r1), "=r"(r2), "=r"(r3) : "r"(a))

__device__ __forceinline__ void mma16816(float c[4], const uint32_t a[4],
                                         uint32_t b0, uint32_t b1) {
    asm volatile(
        "mma.sync.aligned.m16n8k16.row.col.f32.bf16.bf16.f32 "
        "{%0,%1,%2,%3}, {%4,%5,%6,%7}, {%8,%9}, {%0,%1,%2,%3};"
        : "+f"(c[0]), "+f"(c[1]), "+f"(c[2]), "+f"(c[3])
        : "r"(a[0]), "r"(a[1]), "r"(a[2]), "r"(a[3]), "r"(b0), "r"(b1));
}

__device__ __forceinline__ float dec_thr(unsigned hi) {
    return __uint_as_float((hi & 0x80000000u) ? (hi & 0x7FFFFFFFu) : ~hi);
}

// ---------------------------------------------------------------------------
// Kernel 1: transpose coords (c,i,f) -> g_T fp32 + g_Tb bf16, [f][i][c]
// ---------------------------------------------------------------------------
__global__ void k_transpose(const float* __restrict__ coords) {
    __shared__ float s[8][512];
    const int i0 = blockIdx.x * 32, d_base = blockIdx.y * 64;
    const int tid = threadIdx.x;
    const int f = tid & 15, il = tid >> 4, gi = i0 + il;

    for (int d0 = d_base; d0 < d_base + 64; d0 += 8) {
        __syncthreads();
        const int col = i0 * NF + tid;
        #pragma unroll
        for (int dd = 0; dd < 8; dd++)
            s[dd][tid] = (col < F * NF)
                ? coords[(size_t)(d0 + dd) * (F * NF) + col] : 0.f;
        __syncthreads();
        if (gi < F) {
            float t[8];
            #pragma unroll
            for (int dd = 0; dd < 8; dd++) t[dd] = s[dd][il * 16 + f];
            float* dst = g_T + ((size_t)f * F + gi) * D + d0;
            ((float4*)dst)[0] = make_float4(t[0], t[1], t[2], t[3]);
            ((float4*)dst)[1] = make_float4(t[4], t[5], t[6], t[7]);
            __nv_bfloat162 h[4];
            #pragma unroll
            for (int q = 0; q < 4; q++)
                h[q] = __nv_bfloat162(__float2bfloat16_rn(t[2*q]),
                                      __float2bfloat16_rn(t[2*q+1]));
            *(uint4*)(g_Tb + ((size_t)f * F + gi) * D + d0) = *(uint4*)h;
        }
    }
}

// ---------------------------------------------------------------------------
// Kernel 2: sq[f][i]
// ---------------------------------------------------------------------------
__global__ void k_sq() {
    const int row = blockIdx.x * 8 + (threadIdx.x >> 5);
    const int lane = threadIdx.x & 31;
    if (row >= NF * F) return;
    const float4* p = (const float4*)(g_T + (size_t)row * D);
    float s = 0.f;
    #pragma unroll
    for (int q = 0; q < 4; q++) {
        float4 v = p[lane + q * 32];
        s += v.x * v.x + v.y * v.y + v.z * v.z + v.w * v.w;
    }
    #pragma unroll
    for (int o = 16; o; o >>= 1) s += __shfl_xor_sync(FULLM, s, o);
    if (lane == 0) g_sq[row] = s;
}

__global__ void k_dummy() { if (threadIdx.x == 0) g_dummy_sink = 1.0f; }

// ---------------------------------------------------------------------------
// Kernel 3: bf16 GEMM -> fp16 raw dots.  64x128 block tile, 8 warps (2m x 4n),
//   warp tile m32n32.  grid (32 i-tiles, 16 filters).  3 blocks/SM.
// ---------------------------------------------------------------------------
__global__ void __launch_bounds__(256, 3) k_gemm() {
    extern __shared__ char sm[];
    const uint32_t smb = smem_u32(sm);

    const int tid = threadIdx.x, lane = tid & 31, wid = tid >> 5;
    const int wm = wid & 1, wn = wid >> 1;
    const int f = blockIdx.y, i0 = blockIdx.x * 64;
    const __nv_bfloat16* Tbf = g_Tb + (size_t)f * F * D;

    // A loader: thread t -> row t>>2 (0..63), quarter t&3 (16B each)
    const int arow = tid >> 2, aq = tid & 3;
    const int arow_g = min(i0 + arow, F - 1);
    const uint32_t stA = (uint32_t)arow * 80u + (uint32_t)aq * 16u;
    const __nv_bfloat16* asrc0 = Tbf + (size_t)arow_g * D + aq * 8;

    // B loader: thread t -> row t>>1 (0..127), half t&1 (32B each)
    const int brow = tid >> 1, bh = tid & 1;
    const uint32_t stB = (uint32_t)brow * 80u + (uint32_t)bh * 32u;

    const uint32_t lm_col = (lane & 16) ? 16u : 0u;
    const uint32_t aBase = smb + SM_A + (uint32_t)(wm * 32 + (lane & 15)) * 80u + lm_col;
    const uint32_t bBase = smb + SM_B + (uint32_t)(wn * 32 + (lane & 15)) * 80u + lm_col;

    __half* sbase = g_scoresh + (size_t)(f * FP + i0) * FP;

    for (int jt = 0; jt < 16; jt++) {
        const int jrow_g = min(jt * 128 + brow, F - 1);
        const __nv_bfloat16* bsrc0 = Tbf + (size_t)jrow_g * D + bh * 16;

        float c[2][4][4];
        #pragma unroll
        for (int mt = 0; mt < 2; mt++)
            #pragma unroll
            for (int nt = 0; nt < 4; nt++)
                #pragma unroll
                for (int e = 0; e < 4; e++) c[mt][nt][e] = 0.f;

        #pragma unroll
        for (int pc = 0; pc < 2; pc++) {
            const int ko = pc * 32;
            CP16(smb + SM_A + (uint32_t)pc * BUFA + stA, asrc0 + ko);
            CP16(smb + SM_B + (uint32_t)pc * BUFB + stB,       bsrc0 + ko);
            CP16(smb + SM_B + (uint32_t)pc * BUFB + stB + 16u, bsrc0 + ko + 8);
            CP_COMMIT();
        }

        #pragma unroll 1
        for (int kc = 0; kc < 16; kc++) {
            if (kc < 15) CP_WAIT1(); else CP_WAIT0();
            __syncthreads();
            if (kc + 2 < 16) {
                const int st = (kc + 2) % 3;
                const int ko = (kc + 2) * 32;
                CP16(smb + SM_A + (uint32_t)st * BUFA + stA, asrc0 + ko);
                CP16(smb + SM_B + (uint32_t)st * BUFB + stB,       bsrc0 + ko);
                CP16(smb + SM_B + (uint32_t)st * BUFB + stB + 16u, bsrc0 + ko + 8);
                CP_COMMIT();
            }
            const uint32_t cbA = (uint32_t)(kc % 3) * BUFA;
            const uint32_t cbB = (uint32_t)(kc % 3) * BUFB;
            #pragma unroll
            for (int ks = 0; ks < 2; ks++) {
                uint32_t a[2][4], b[4][2], t0, t1, t2, t3;
                #pragma unroll
                for (int mt = 0; mt < 2; mt++)
                    LDSM4(a[mt][0], a[mt][1], a[mt][2], a[mt][3],
                          aBase + cbA + (uint32_t)mt * 1280u + (uint32_t)ks * 32u);
                #pragma unroll
                for (int p = 0; p < 2; p++) {
                    LDSM4(t0, t1, t2, t3,
                          bBase + cbB + (uint32_t)p * 1280u + (uint32_t)ks * 32u);
                    b[2*p][0] = t0; b[2*p][1] = t2;
                    b[2*p+1][0] = t1; b[2*p+1][1] = t3;
                }
                #pragma unroll
                for (int mt = 0; mt < 2; mt++)
                    #pragma unroll
                    for (int nt = 0; nt < 4; nt++)
                        mma16816(c[mt][nt], a[mt], b[nt][0], b[nt][1]);
            }
        }
        __syncthreads();   // ring safety before next jt prologue

        // dump raw dots as fp16
        const int colb = jt * 128 + wn * 32 + 2 * (lane & 3);
        #pragma unroll
        for (int mt = 0; mt < 2; mt++) {
            const int r0 = wm * 32 + mt * 16 + (lane >> 2);
            __half* p0 = sbase + (size_t)r0 * FP + colb;
            __half* p1 = p0 + (size_t)8 * FP;
            #pragma unroll
            for (int nt = 0; nt < 4; nt++) {
                *(__half2*)(p0 + nt * 8) =
                    __floats2half2_rn(c[mt][nt][0], c[mt][nt][1]);
                *(__half2*)(p1 + nt * 8) =
                    __floats2half2_rn(c[mt][nt][2], c[mt][nt][3]);
            }
        }
    }
}

// ---------------------------------------------------------------------------
// Kernel 4: selection — one warp per (row, filter); top-16 shortlist
// ---------------------------------------------------------------------------
__global__ void __launch_bounds__(256) k_select() {
    const int wid = threadIdx.x >> 5, lane = threadIdx.x & 31;
    const int row = blockIdx.x * 8 + wid;
    if (row >= NF * F) return;
    const int f = row / F, i = row - f * F;
    const __half* sc = g_scoresh + (size_t)(f * FP + i) * FP;
    const float* sqf = g_sq + f * F;

    unsigned long long Lv = SENT;
    unsigned long long L15 = SENT;
    float thr = __int_as_float(0x7F800000);

    #pragma unroll 1
    for (int it = 0; it < 16; it++) {
        const int j0 = it * 128 + lane * 4;
        float s[4];
        if (j0 < F) {
            const uint2 hv = *(const uint2*)(sc + j0);
            const float2 c01 = __half22float2(*(const __half2*)&hv.x);
            const float2 c23 = __half22float2(*(const __half2*)&hv.y);
            const float4 q = *(const float4*)(sqf + j0);
            s[0] = fmaf(-2.f, c01.x, q.x); s[1] = fmaf(-2.f, c01.y, q.y);
            s[2] = fmaf(-2.f, c23.x, q.z); s[3] = fmaf(-2.f, c23.y, q.w);
        } else {
            s[0] = s[1] = s[2] = s[3] = __int_as_float(0x7F800000);
        }
        unsigned pend = (s[0] <= thr ? 1u : 0u) | (s[1] <= thr ? 2u : 0u)
                      | (s[2] <= thr ? 4u : 0u) | (s[3] <= thr ? 8u : 0u);
        while (true) {
            const unsigned any = __ballot_sync(FULLM, pend != 0u);
            if (!any) break;
            const int src = __ffs(any) - 1;
            const unsigned spend = __shfl_sync(FULLM, pend, src);
            const int e = __ffs(spend) - 1;
            if (lane == src) pend &= pend - 1;
            const float vx = (e == 0) ? s[0] : (e == 1) ? s[1]
                           : (e == 2) ? s[2] : s[3];
            const float sv = __shfl_sync(FULLM, vx, src);
            unsigned u = __float_as_uint(sv);
            u ^= ((unsigned)(((int)u) >> 31)) | 0x80000000u;
            const unsigned long long key =
                ((unsigned long long)u << 32)
                | (unsigned)(it * 128 + src * 4 + e);
            if (key < L15) {
                const unsigned bal =
                    __ballot_sync(FULLM, (lane < 16) && (Lv < key));
                const int pos = __popc(bal);
                const unsigned long long up = __shfl_up_sync(FULLM, Lv, 1);
                if (lane < 16)
                    Lv = (lane < pos) ? Lv : ((lane == pos) ? key : up);
                L15 = __shfl_sync(FULLM, Lv, 15);
                thr = dec_thr((unsigned)(L15 >> 32));
                pend &= (s[0] <= thr ? 1u : 0u) | (s[1] <= thr ? 2u : 0u)
                      | (s[2] <= thr ? 4u : 0u) | (s[3] <= thr ? 8u : 0u);
            }
        }
    }
    if (lane < 16)
        g_cand[row * SL + lane] = (int)(unsigned)(Lv & 0xFFFFFFFFull);
}

// ---------------------------------------------------------------------------
// Kernel 5: exact fp32 rescore of the shortlist; emit top-8 indices
// ---------------------------------------------------------------------------
__global__ void __launch_bounds__(256) k_rescore() {
    const int wid = threadIdx.x >> 5, lane = threadIdx.x & 31;
    const int row = blockIdx.x * 8 + wid;
    if (row >= NF * F) return;
    const int f = row / F, i = row - f * F;
    const float* xi = g_T + (size_t)row * D;
    float4 xa[4];
    #pragma unroll
    for (int q = 0; q < 4; q++) xa[q] = *(const float4*)(xi + lane * 16 + q * 4);

    unsigned long long keys[SL];
    #pragma unroll 1
    for (int c = 0; c < SL; c += 2) {
        const int j0 = g_cand[row * SL + c];
        const int j1 = g_cand[row * SL + c + 1];
        const float* x0 = g_T + ((size_t)f * F + j0) * D;
        const float* x1 = g_T + ((size_t)f * F + j1) * D;
        float p0 = 0.f, p1 = 0.f;
        #pragma unroll
        for (int q = 0; q < 4; q++) {
            float4 a = xa[q];
            float4 v0 = *(const float4*)(x0 + lane * 16 + q * 4);
            float4 v1 = *(const float4*)(x1 + lane * 16 + q * 4);
            p0 = fmaf(a.x, v0.x, p0); p1 = fmaf(a.x, v1.x, p1);
            p0 = fmaf(a.y, v0.y, p0); p1 = fmaf(a.y, v1.y, p1);
            p0 = fmaf(a.z, v0.z, p0); p1 = fmaf(a.z, v1.z, p1);
            p0 = fmaf(a.w, v0.w, p0); p1 = fmaf(a.w, v1.w, p1);
        }
        #pragma unroll
        for (int o = 16; o; o >>= 1) {
            p0 += __shfl_xor_sync(FULLM, p0, o);
            p1 += __shfl_xor_sync(FULLM, p1, o);
        }
        const float s0 = fmaf(-2.f, p0, g_sq[f * F + j0]);
        const float s1 = fmaf(-2.f, p1, g_sq[f * F + j1]);
        unsigned u0 = __float_as_uint(s0);
        u0 ^= ((unsigned)(((int)u0) >> 31)) | 0x80000000u;
        unsigned u1 = __float_as_uint(s1);
        u1 ^= ((unsigned)(((int)u1) >> 31)) | 0x80000000u;
        keys[c]     = ((unsigned long long)u0 << 32) | (unsigned)j0;
        keys[c + 1] = ((unsigned long long)u1 << 32) | (unsigned)j1;
    }
    if (lane == 0) {
        #pragma unroll
        for (int k = 0; k < KNN; k++) {
            int m = k;
            #pragma unroll
            for (int c = k + 1; c < SL; c++) if (keys[c] < keys[m]) m = c;
            const unsigned long long tk = keys[m];
            keys[m] = keys[k]; keys[k] = tk;
            g_idx[((size_t)i * KNN + k) * NF + f] =
                (int)(unsigned)(tk & 0xFFFFFFFFull);
        }
    }
}

// ---------------------------------------------------------------------------
// Kernel 6: gather — warp covers 32 contiguous (ik,f) pairs
// ---------------------------------------------------------------------------
__global__ void k_gather(const float* __restrict__ inp, float* __restrict__ out) {
    const int wid = threadIdx.x >> 5, lane = threadIdx.x & 31;
    const int ik = blockIdx.x * 16 + wid * 2 + (lane >> 4);
    const int f  = lane & 15;
    const int j  = g_idx[ik * NF + f];
    const float* src = inp + (size_t)j * NF + f;
    float* dst = out + (size_t)ik * NF + f;
    #pragma unroll 8
    for (int b = 0; b < 64; b++)
        dst[(size_t)b * (F * KNN * NF)] = src[(size_t)b * (F * NF)];
}

// ---------------------------------------------------------------------------
extern "C" void kernel_launch(void* const* d_in, const int* in_sizes, int n_in,
                              void* d_out, int out_size) {
    const float* inputs = (const float*)d_in[0];
    const float* coords = (const float*)d_in[1];
    if (n_in >= 2 && in_sizes[0] == D * F * NF) {
        const float* t = inputs; inputs = coords; coords = t;
    }
    (void)out_size;

    k_transpose<<<dim3((F + 31) / 32, D / 64), 512>>>(coords);
    k_sq<<<(NF * F + 7) / 8, 256>>>();
    k_dummy<<<1, 32>>>();
    k_gemm<<<dim3(32, NF), 256, SM_TOTAL>>>();
    k_select<<<(NF * F + 7) / 8, 256>>>();
    k_rescore<<<(NF * F + 7) / 8, 256>>>();
    k_gather<<<F * KNN / 16, 256>>>(inputs, (float*)d_out);
}

// round 16
// speedup vs baseline: 1.2618x; 1.2618x over previous
#include <cuda_runtime.h>
#include <cuda_bf16.h>
#include <cuda_fp16.h>
#include <cstdint>

#define D   512
#define F   2000
#define NF  16
#define KNN 8
#define SL  16
#define FP  2048
#define NT  16        // 2048/128 tiles per dim
#define NPAIR (NT * (NT + 1) / 2)   // 136

// ---- scratch ----
__device__ float         g_T [(size_t)NF * F * D];
__device__ __nv_bfloat16 g_Tb[(size_t)NF * F * D];
__device__ float         g_sq[NF * F];
__device__ __half        g_scoresh[(size_t)NF * FP * FP];
__device__ int           g_cand[NF * F * SL];
__device__ int           g_idx [F * KNN * NF];
__device__ float         g_dummy_sink;

#define SENT 0xFF800000FFFFFFFFull
#define FULLM 0xFFFFFFFFu

// ---- smem for k_gemm: 3-stage A/B rings + fp16 transpose stage ----
#define SM_A    0         // 3 x 10240 = 30720
#define SM_B    30720     // 3 x 10240 = 30720
#define SM_STG  61440     // 128 x 136 x 2 = 34816
#define SM_TOTAL 96256
#define BUFB    10240u

__device__ __forceinline__ uint32_t smem_u32(const void* p) {
    uint32_t a;
    asm("{ .reg .u64 t; cvta.to.shared.u64 t, %1; cvt.u32.u64 %0, t; }"
        : "=r"(a) : "l"(p));
    return a;
}
#define CP16(dst, src) \
    asm volatile("cp.async.cg.shared.global [%0], [%1], 16;" :: "r"(dst), "l"(src))
#define CP_COMMIT() asm volatile("cp.async.commit_group;" ::: "memory")
#define CP_WAIT0()  asm volatile("cp.async.wait_group 0;" ::: "memory")
#define CP_WAIT1()  asm volatile("cp.async.wait_group 1;" ::: "memory")
#define LDSM4(r0, r1, r2, r3, a) \
    asm volatile("ldmatrix.sync.aligned.m8n8.x4.shared.b16 {%0,%1,%2,%3}, [%4];" \
        : "=r"(r0), "=r"(r1), "=r"(r2), "=r"(r3) : "r"(a))

__device__ __forceinline__ void mma16816(float c[4], const uint32_t a[4],
                                         uint32_t b0, uint32_t b1) {
    asm volatile(
        "mma.sync.aligned.m16n8k16.row.col.f32.bf16.bf16.f32 "
        "{%0,%1,%2,%3}, {%4,%5,%6,%7}, {%8,%9}, {%0,%1,%2,%3};"
        : "+f"(c[0]), "+f"(c[1]), "+f"(c[2]), "+f"(c[3])
        : "r"(a[0]), "r"(a[1]), "r"(a[2]), "r"(a[3]), "r"(b0), "r"(b1));
}

__device__ __forceinline__ float dec_thr(unsigned hi) {
    return __uint_as_float((hi & 0x80000000u) ? (hi & 0x7FFFFFFFu) : ~hi);
}

// ---------------------------------------------------------------------------
// Kernel 1: transpose coords (c,i,f) -> g_T fp32 + g_Tb bf16, [f][i][c]
// ---------------------------------------------------------------------------
__global__ void k_transpose(const float* __restrict__ coords) {
    __shared__ float s[8][512];
    const int i0 = blockIdx.x * 32, d_base = blockIdx.y * 64;
    const int tid = threadIdx.x;
    const int f = tid & 15, il = tid >> 4, gi = i0 + il;

    for (int d0 = d_base; d0 < d_base + 64; d0 += 8) {
        __syncthreads();
        const int col = i0 * NF + tid;
        #pragma unroll
        for (int dd = 0; dd < 8; dd++)
            s[dd][tid] = (col < F * NF)
                ? coords[(size_t)(d0 + dd) * (F * NF) + col] : 0.f;
        __syncthreads();
        if (gi < F) {
            float t[8];
            #pragma unroll
            for (int dd = 0; dd < 8; dd++) t[dd] = s[dd][il * 16 + f];
            float* dst = g_T + ((size_t)f * F + gi) * D + d0;
            ((float4*)dst)[0] = make_float4(t[0], t[1], t[2], t[3]);
            ((float4*)dst)[1] = make_float4(t[4], t[5], t[6], t[7]);
            __nv_bfloat162 h[4];
            #pragma unroll
            for (int q = 0; q < 4; q++)
                h[q] = __nv_bfloat162(__float2bfloat16_rn(t[2*q]),
                                      __float2bfloat16_rn(t[2*q+1]));
            *(uint4*)(g_Tb + ((size_t)f * F + gi) * D + d0) = *(uint4*)h;
        }
    }
}

// ---------------------------------------------------------------------------
// Kernel 2: sq[f][i]
// ---------------------------------------------------------------------------
__global__ void k_sq() {
    const int row = blockIdx.x * 8 + (threadIdx.x >> 5);
    const int lane = threadIdx.x & 31;
    if (row >= NF * F) return;
    const float4* p = (const float4*)(g_T + (size_t)row * D);
    float s = 0.f;
    #pragma unroll
    for (int q = 0; q < 4; q++) {
        float4 v = p[lane + q * 32];
        s += v.x * v.x + v.y * v.y + v.z * v.z + v.w * v.w;
    }
    #pragma unroll
    for (int o = 16; o; o >>= 1) s += __shfl_xor_sync(FULLM, s, o);
    if (lane == 0) g_sq[row] = s;
}

__global__ void k_dummy() { if (threadIdx.x == 0) g_dummy_sink = 1.0f; }

// ---------------------------------------------------------------------------
// Kernel 3: symmetric bf16 GEMM — one block per tile pair (ti <= tj).
//   128x128 tile, 8 warps m64n32 (R9 mainloop). Writes tile + its transpose.
// ---------------------------------------------------------------------------
__global__ void __launch_bounds__(256, 2) k_gemm() {
    extern __shared__ char sm[];
    const uint32_t smb = smem_u32(sm);
    __half* stage = (__half*)(sm + SM_STG);

    const int tid = threadIdx.x, lane = tid & 31, wid = tid >> 5;
    const int wm = wid & 1, wn = wid >> 1;
    const int f = blockIdx.y;

    // triangular decode: blockIdx.x -> (ti, tj), ti <= tj
    int b = blockIdx.x, ti = 0;
    while (b >= NT - ti) { b -= NT - ti; ti++; }
    const int tj = ti + b;
    const int i0 = ti * 128, j0 = tj * 128;

    const __nv_bfloat16* Tbf = g_Tb + (size_t)f * F * D;

    // loaders: thread t covers row t>>1 (0..127), half t&1 (32B of 64B row)
    const int lrow = tid >> 1, lq = tid & 1;
    const uint32_t st_off = (uint32_t)lrow * 80u + (uint32_t)lq * 32u;
    const __nv_bfloat16* asrc0 = Tbf + (size_t)min(i0 + lrow, F - 1) * D + lq * 16;
    const __nv_bfloat16* bsrc0 = Tbf + (size_t)min(j0 + lrow, F - 1) * D + lq * 16;

    const uint32_t lm_col = (lane & 16) ? 16u : 0u;
    const uint32_t aBase = smb + SM_A + (uint32_t)(wm * 64 + (lane & 15)) * 80u + lm_col;
    const uint32_t bBase = smb + SM_B + (uint32_t)(wn * 32 + (lane & 15)) * 80u + lm_col;

    float c[4][4][4];
    #pragma unroll
    for (int mt = 0; mt < 4; mt++)
        #pragma unroll
        for (int nt = 0; nt < 4; nt++)
            #pragma unroll
            for (int e = 0; e < 4; e++) c[mt][nt][e] = 0.f;

    // prologue: prefetch chunks 0,1
    #pragma unroll
    for (int pc = 0; pc < 2; pc++) {
        const uint32_t nb = (uint32_t)pc * BUFB;
        const int ko = pc * 32;
        CP16(smb + SM_A + nb + st_off,       asrc0 + ko);
        CP16(smb + SM_A + nb + st_off + 16u, asrc0 + ko + 8);
        CP16(smb + SM_B + nb + st_off,       bsrc0 + ko);
        CP16(smb + SM_B + nb + st_off + 16u, bsrc0 + ko + 8);
        CP_COMMIT();
    }

    #pragma unroll 1
    for (int kc = 0; kc < 16; kc++) {
        if (kc < 15) CP_WAIT1(); else CP_WAIT0();
        __syncthreads();
        if (kc + 2 < 16) {
            const uint32_t nb = (uint32_t)((kc + 2) % 3) * BUFB;
            const int ko = (kc + 2) * 32;
            CP16(smb + SM_A + nb + st_off,       asrc0 + ko);
            CP16(smb + SM_A + nb + st_off + 16u, asrc0 + ko + 8);
            CP16(smb + SM_B + nb + st_off,       bsrc0 + ko);
            CP16(smb + SM_B + nb + st_off + 16u, bsrc0 + ko + 8);
            CP_COMMIT();
        }
        const uint32_t cb = (uint32_t)(kc % 3) * BUFB;
        #pragma unroll
        for (int ks = 0; ks < 2; ks++) {
            uint32_t a[4][4], bb[4][2], t0, t1, t2, t3;
            #pragma unroll
            for (int mt = 0; mt < 4; mt++)
                LDSM4(a[mt][0], a[mt][1], a[mt][2], a[mt][3],
                      aBase + cb + (uint32_t)mt * 1280u + (uint32_t)ks * 32u);
            #pragma unroll
            for (int p = 0; p < 2; p++) {
                LDSM4(t0, t1, t2, t3,
                      bBase + cb + (uint32_t)p * 1280u + (uint32_t)ks * 32u);
                bb[2*p][0] = t0; bb[2*p][1] = t2;
                bb[2*p+1][0] = t1; bb[2*p+1][1] = t3;
            }
            #pragma unroll
            for (int mt = 0; mt < 4; mt++)
                #pragma unroll
                for (int nt = 0; nt < 4; nt++)
                    mma16816(c[mt][nt], a[mt], bb[nt][0], bb[nt][1]);
        }
    }
    __syncthreads();   // rings dead; stage reuse is safe after this

    // stage tile as fp16 [128][136]
    const int colw = wn * 32 + 2 * (lane & 3);
    #pragma unroll
    for (int mt = 0; mt < 4; mt++) {
        const int r0 = wm * 64 + mt * 16 + (lane >> 2);
        #pragma unroll
        for (int nt = 0; nt < 4; nt++) {
            *(__half2*)(stage + r0 * 136 + colw + nt * 8) =
                __floats2half2_rn(c[mt][nt][0], c[mt][nt][1]);
            *(__half2*)(stage + (r0 + 8) * 136 + colw + nt * 8) =
                __floats2half2_rn(c[mt][nt][2], c[mt][nt][3]);
        }
    }
    __syncthreads();

    // direct write: rows i0+r, cols j0..j0+127
    {
        const int row = tid >> 1, half_ = tid & 1;
        const uint4* sv = (const uint4*)(stage + row * 136 + half_ * 64);
        uint4* dp = (uint4*)(g_scoresh
            + ((size_t)f * FP + i0 + row) * FP + j0 + half_ * 64);
        #pragma unroll
        for (int q = 0; q < 8; q++) dp[q] = sv[q];
    }
    // transposed write: rows j0+c, cols i0..i0+127
    if (ti != tj) {
        const int cc = tid >> 1, part = tid & 1;
        __half* tp = g_scoresh
            + ((size_t)f * FP + j0 + cc) * FP + i0 + part * 64;
        #pragma unroll
        for (int q = 0; q < 8; q++) {
            __half tmp[8];
            #pragma unroll
            for (int s = 0; s < 8; s++)
                tmp[s] = stage[(part * 64 + q * 8 + s) * 136 + cc];
            *(uint4*)(tp + q * 8) = *(uint4*)tmp;
        }
    }
}

// ---------------------------------------------------------------------------
// Kernel 4: selection — one warp per (row, filter); top-16 shortlist
// ---------------------------------------------------------------------------
__global__ void __launch_bounds__(256) k_select() {
    const int wid = threadIdx.x >> 5, lane = threadIdx.x & 31;
    const int row = blockIdx.x * 8 + wid;
    if (row >= NF * F) return;
    const int f = row / F, i = row - f * F;
    const __half* sc = g_scoresh + (size_t)(f * FP + i) * FP;
    const float* sqf = g_sq + f * F;

    unsigned long long Lv = SENT;
    unsigned long long L15 = SENT;
    float thr = __int_as_float(0x7F800000);

    #pragma unroll 1
    for (int it = 0; it < 16; it++) {
        const int j0 = it * 128 + lane * 4;
        float s[4];
        if (j0 < F) {
            const uint2 hv = *(const uint2*)(sc + j0);
            const float2 c01 = __half22float2(*(const __half2*)&hv.x);
            const float2 c23 = __half22float2(*(const __half2*)&hv.y);
            const float4 q = *(const float4*)(sqf + j0);
            s[0] = fmaf(-2.f, c01.x, q.x); s[1] = fmaf(-2.f, c01.y, q.y);
            s[2] = fmaf(-2.f, c23.x, q.z); s[3] = fmaf(-2.f, c23.y, q.w);
        } else {
            s[0] = s[1] = s[2] = s[3] = __int_as_float(0x7F800000);
        }
        unsigned pend = (s[0] <= thr ? 1u : 0u) | (s[1] <= thr ? 2u : 0u)
                      | (s[2] <= thr ? 4u : 0u) | (s[3] <= thr ? 8u : 0u);
        while (true) {
            const unsigned any = __ballot_sync(FULLM, pend != 0u);
            if (!any) break;
            const int src = __ffs(any) - 1;
            const unsigned spend = __shfl_sync(FULLM, pend, src);
            const int e = __ffs(spend) - 1;
            if (lane == src) pend &= pend - 1;
            const float vx = (e == 0) ? s[0] : (e == 1) ? s[1]
                           : (e == 2) ? s[2] : s[3];
            const float sv = __shfl_sync(FULLM, vx, src);
            unsigned u = __float_as_uint(sv);
            u ^= ((unsigned)(((int)u) >> 31)) | 0x80000000u;
            const unsigned long long key =
                ((unsigned long long)u << 32)
                | (unsigned)(it * 128 + src * 4 + e);
            if (key < L15) {
                const unsigned bal =
                    __ballot_sync(FULLM, (lane < 16) && (Lv < key));
                const int pos = __popc(bal);
                const unsigned long long up = __shfl_up_sync(FULLM, Lv, 1);
                if (lane < 16)
                    Lv = (lane < pos) ? Lv : ((lane == pos) ? key : up);
                L15 = __shfl_sync(FULLM, Lv, 15);
                thr = dec_thr((unsigned)(L15 >> 32));
                pend &= (s[0] <= thr ? 1u : 0u) | (s[1] <= thr ? 2u : 0u)
                      | (s[2] <= thr ? 4u : 0u) | (s[3] <= thr ? 8u : 0u);
            }
        }
    }
    if (lane < 16)
        g_cand[row * SL + lane] = (int)(unsigned)(Lv & 0xFFFFFFFFull);
}

// ---------------------------------------------------------------------------
// Kernel 5: exact fp32 rescore of the shortlist; emit top-8 indices
// ---------------------------------------------------------------------------
__global__ void __launch_bounds__(256) k_rescore() {
    const int wid = threadIdx.x >> 5, lane = threadIdx.x & 31;
    const int row = blockIdx.x * 8 + wid;
    if (row >= NF * F) return;
    const int f = row / F, i = row - f * F;
    const float* xi = g_T + (size_t)row * D;
    float4 xa[4];
    #pragma unroll
    for (int q = 0; q < 4; q++) xa[q] = *(const float4*)(xi + lane * 16 + q * 4);

    unsigned long long keys[SL];
    #pragma unroll 1
    for (int c = 0; c < SL; c += 2) {
        const int j0 = g_cand[row * SL + c];
        const int j1 = g_cand[row * SL + c + 1];
        const float* x0 = g_T + ((size_t)f * F + j0) * D;
        const float* x1 = g_T + ((size_t)f * F + j1) * D;
        float p0 = 0.f, p1 = 0.f;
        #pragma unroll
        for (int q = 0; q < 4; q++) {
            float4 a = xa[q];
            float4 v0 = *(const float4*)(x0 + lane * 16 + q * 4);
            float4 v1 = *(const float4*)(x1 + lane * 16 + q * 4);
            p0 = fmaf(a.x, v0.x, p0); p1 = fmaf(a.x, v1.x, p1);
            p0 = fmaf(a.y, v0.y, p0); p1 = fmaf(a.y, v1.y, p1);
            p0 = fmaf(a.z, v0.z, p0); p1 = fmaf(a.z, v1.z, p1);
            p0 = fmaf(a.w, v0.w, p0); p1 = fmaf(a.w, v1.w, p1);
        }
        #pragma unroll
        for (int o = 16; o; o >>= 1) {
            p0 += __shfl_xor_sync(FULLM, p0, o);
            p1 += __shfl_xor_sync(FULLM, p1, o);
        }
        const float s0 = fmaf(-2.f, p0, g_sq[f * F + j0]);
        const float s1 = fmaf(-2.f, p1, g_sq[f * F + j1]);
        unsigned u0 = __float_as_uint(s0);
        u0 ^= ((unsigned)(((int)u0) >> 31)) | 0x80000000u;
        unsigned u1 = __float_as_uint(s1);
        u1 ^= ((unsigned)(((int)u1) >> 31)) | 0x80000000u;
        keys[c]     = ((unsigned long long)u0 << 32) | (unsigned)j0;
        keys[c + 1] = ((unsigned long long)u1 << 32) | (unsigned)j1;
    }
    if (lane == 0) {
        #pragma unroll
        for (int k = 0; k < KNN; k++) {
            int m = k;
            #pragma unroll
            for (int c = k + 1; c < SL; c++) if (keys[c] < keys[m]) m = c;
            const unsigned long long tk = keys[m];
            keys[m] = keys[k]; keys[k] = tk;
            g_idx[((size_t)i * KNN + k) * NF + f] =
                (int)(unsigned)(tk & 0xFFFFFFFFull);
        }
    }
}

// ---------------------------------------------------------------------------
// Kernel 6: gather — warp covers 32 contiguous (ik,f) pairs
// ---------------------------------------------------------------------------
__global__ void k_gather(const float* __restrict__ inp, float* __restrict__ out) {
    const int wid = threadIdx.x >> 5, lane = threadIdx.x & 31;
    const int ik = blockIdx.x * 16 + wid * 2 + (lane >> 4);
    const int f  = lane & 15;
    const int j  = g_idx[ik * NF + f];
    const float* src = inp + (size_t)j * NF + f;
    float* dst = out + (size_t)ik * NF + f;
    #pragma unroll 8
    for (int b = 0; b < 64; b++)
        dst[(size_t)b * (F * KNN * NF)] = src[(size_t)b * (F * NF)];
}

// ---------------------------------------------------------------------------
extern "C" void kernel_launch(void* const* d_in, const int* in_sizes, int n_in,
                              void* d_out, int out_size) {
    const float* inputs = (const float*)d_in[0];
    const float* coords = (const float*)d_in[1];
    if (n_in >= 2 && in_sizes[0] == D * F * NF) {
        const float* t = inputs; inputs = coords; coords = t;
    }
    (void)out_size;

    static bool attr_done = false;
    if (!attr_done) {
        cudaFuncSetAttribute(k_gemm,
            cudaFuncAttributeMaxDynamicSharedMemorySize, SM_TOTAL);
        attr_done = true;
    }

    k_transpose<<<dim3((F + 31) / 32, D / 64), 512>>>(coords);
    k_sq<<<(NF * F + 7) / 8, 256>>>();
    k_dummy<<<1, 32>>>();
    k_gemm<<<dim3(NPAIR, NF), 256, SM_TOTAL>>>();
    k_select<<<(NF * F + 7) / 8, 256>>>();
    k_rescore<<<(NF * F + 7) / 8, 256>>>();
    k_gather<<<F * KNN / 16, 256>>>(inputs, (float*)d_out);
}